// round 3
// baseline (speedup 1.0000x reference)
#include <cuda_runtime.h>

#define NN 128
#define TRI (NN * (NN + 1) / 2)   // 8256 cells per triangular table

__device__ __forceinline__ int triRow(int a) {
    // index of cell (a, a) in triangular packing
    return a * (2 * NN - a + 1) / 2;
}

#define NEGC    (-9999.0f)
#define THRESHC (-9000.0f)

// One DP step for span width k, with G lanes cooperating per span.
// A warp covers 32/G spans; reductions are log2(G) butterfly steps.
template<int G>
__device__ __forceinline__ void step_body(
    const float* __restrict__ T00, const float* __restrict__ T01,
    const float* __restrict__ T10, const float* __restrict__ T11,
    float* __restrict__ W00, float* __restrict__ W01,
    float* __restrict__ W10, float* __restrict__ W11,
    const float* __restrict__ vin,
    float* __restrict__ outS, float* __restrict__ outB,
    int has_bt, int k, int tid)
{
    const int nspans = NN - k;
    // whole-warp early out (converged: all lanes of the warp share this test)
    if (((tid & ~31) / G) >= nspans) return;

    const int gid_raw = tid / G;
    const int lig = tid % G;
    const bool lead = (lig == 0) && (gid_raw < nspans);
    const int i = min(gid_raw, nspans - 1);   // clamp dup groups (writes gated by lead)
    const int j = i + k;

    const float vL = vin[j * NN + i];   // left arc  (head j)
    const float vR = vin[i * NN + j];   // right arc (head i)
    const int rpi = triRow(i);

    const float NINF = __int_as_float(0xff800000);
    float v00 = NINF, v10 = NINF, v01 = NINF, v11 = NINF;
    int   m00 = NN,   m10 = NN,   m01 = NN,   m11 = NN;

    // incremental triangular indices: q = i + m, m = lig, lig+G, ...
    int m   = lig;
    int q0  = i + lig;
    int A   = triRow(q0) + (j - q0);        // tri(q, j)
    int B   = A + (NN - 1 - q0);            // tri(q+1, j)
    int dA  = (G * (257 - 2 * q0 - G)) / 2 - G;   // A(next) - A(cur)
    int idx = rpi + lig;                    // rpi + m

    for (; m < k; m += G) {
        const float s11 = T11[idx];
        const float s01 = T01[B];
        const float base = s11 + s01;
        // preserve reference rounding order: ((s11+s01)+v)+5.0
        float a0 = (base + vL) + 5.0f;
        float a1 = (base + vR) + 5.0f;
        if (a0 > v00) { v00 = a0; m00 = m; }
        if (a1 > v10) { v10 = a1; m10 = m; }
        if (m >= 1) {
            float c01 = T01[idx] + T00[A];
            float c11 = T10[idx] + T11[A];
            if (c01 > v01) { v01 = c01; m01 = m; }
            if (c11 > v11) { v11 = c11; m11 = m; }
        }
        A += dA; B += dA - G; dA -= G * G; idx += G;
    }

    #pragma unroll
    for (int off = G / 2; off; off >>= 1) {
        float ov; int om;
        ov = __shfl_xor_sync(0xffffffffu, v00, off);
        om = __shfl_xor_sync(0xffffffffu, m00, off);
        if (ov > v00 || (ov == v00 && om < m00)) { v00 = ov; m00 = om; }
        ov = __shfl_xor_sync(0xffffffffu, v10, off);
        om = __shfl_xor_sync(0xffffffffu, m10, off);
        if (ov > v10 || (ov == v10 && om < m10)) { v10 = ov; m10 = om; }
        ov = __shfl_xor_sync(0xffffffffu, v01, off);
        om = __shfl_xor_sync(0xffffffffu, m01, off);
        if (ov > v01 || (ov == v01 && om < m01)) { v01 = ov; m01 = om; }
        ov = __shfl_xor_sync(0xffffffffu, v11, off);
        om = __shfl_xor_sync(0xffffffffu, m11, off);
        if (ov > v11 || (ov == v11 && om < m11)) { v11 = ov; m11 = om; }
    }

    if (lead) {
        // sequential-update quirks of the reference:
        // (0,1) at q=i sees the (0,0) cell after ONLY the q=i update
        float base0 = T11[rpi] + T01[rpi + (NN - i) + (k - 1)];
        float p000 = (base0 + vL) + 5.0f;
        p000 = fmaxf(p000, NEGC);
        const float part00 = (p000 > THRESHC) ? p000 : NEGC;
        if (part00 > v01 || (part00 == v01 && 0 < m01)) { v01 = part00; m01 = 0; }
        // (1,1) at q=j sees the fully updated (1,0) cell
        const float new10 = (v10 > THRESHC) ? v10 : NEGC;
        if (new10 > v11) { v11 = new10; m11 = k; }

        const float s00 = (v00 > THRESHC) ? v00 : NEGC;
        const float s10 = (v10 > THRESHC) ? v10 : NEGC;
        const float s01 = (v01 > THRESHC) ? v01 : NEGC;
        const float s11 = (v11 > THRESHC) ? v11 : NEGC;
        const int t00 = (v00 > THRESHC) ? (i + m00) : 0;
        const int t10 = (v10 > THRESHC) ? (i + m10) : 0;
        const int t01 = (v01 > THRESHC) ? (i + m01) : 0;
        const int t11 = (v11 > THRESHC) ? (i + m11) : 0;

        const int tij = rpi + k;   // tri(i, j)
        W00[tij] = s00; W01[tij] = s01; W10[tij] = s10; W11[tij] = s11;

        const size_t o = ((size_t)(i * NN + j)) * 4;
        outS[o + 0] = s00; outS[o + 1] = s01;
        outS[o + 2] = s10; outS[o + 3] = s11;
        if (has_bt) {
            outB[o + 0] = (float)t00; outB[o + 1] = (float)t01;
            outB[o + 2] = (float)t10; outB[o + 3] = (float)t11;
        }
    }
}

__global__ void __launch_bounds__(1024, 1)
eisner_kernel(const float* __restrict__ vin_all,
              float* __restrict__ out,
              int has_bt, int bt_off)
{
    extern __shared__ float sm[];
    float* T00 = sm;               // S[:,:,0,0]
    float* T01 = sm + TRI;         // S[:,:,0,1]
    float* T10 = sm + 2 * TRI;     // S[:,:,1,0]
    float* T11 = sm + 3 * TRI;     // S[:,:,1,1]

    const int b = blockIdx.x;
    const float* __restrict__ vin = vin_all + (size_t)b * NN * NN;
    float* __restrict__ outS = out + (size_t)b * NN * NN * 4;
    float* __restrict__ outB = out + (size_t)bt_off + (size_t)b * NN * NN * 4;

    const int tid = threadIdx.x;

    // ---- init: triangular tables = NEG, diagonal = 0 ----
    for (int t = tid; t < 4 * TRI; t += blockDim.x) sm[t] = NEGC;
    __syncthreads();
    for (int i = tid; i < NN; i += blockDim.x) {
        int d = triRow(i);
        T00[d] = 0.0f; T01[d] = 0.0f; T10[d] = 0.0f; T11[d] = 0.0f;
    }
    // ---- init output: scores = NEG (diag 0), backtrace = 0 ----
    for (int t = tid; t < NN * NN * 4; t += blockDim.x) {
        int i = t >> 9;               // t / (NN*4)
        int j = (t >> 2) & (NN - 1);  // (t/4) % NN
        outS[t] = (i == j) ? 0.0f : NEGC;
    }
    if (has_bt) {
        for (int t = tid; t < NN * NN * 4; t += blockDim.x) outB[t] = 0.0f;
    }
    __syncthreads();

    // G policy: largest power of two with nspans * G <= 1024
    //   k <= 63  (nspans >= 65) -> G = 8
    //   64 <= k <= 95 (nspans 33..64) -> G = 16
    //   k >= 96 (nspans <= 32) -> G = 32
    for (int k = 1; k < NN; ++k) {
        if (k <= 63)
            step_body<8 >(T00, T01, T10, T11, T00, T01, T10, T11, vin, outS, outB, has_bt, k, tid);
        else if (k <= 95)
            step_body<16>(T00, T01, T10, T11, T00, T01, T10, T11, vin, outS, outB, has_bt, k, tid);
        else
            step_body<32>(T00, T01, T10, T11, T00, T01, T10, T11, vin, outS, outB, has_bt, k, tid);
        __syncthreads();
    }
}

extern "C" void kernel_launch(void* const* d_in, const int* in_sizes, int n_in,
                              void* d_out, int out_size)
{
    const float* vin = (const float*)d_in[0];
    float* out = (float*)d_out;
    const int B = in_sizes[0] / (NN * NN);          // 64
    const int score_elems = B * NN * NN * 4;        // scores region size
    const int has_bt = (out_size >= 2 * score_elems) ? 1 : 0;

    const int smem_bytes = 4 * TRI * sizeof(float); // 132096 B
    cudaFuncSetAttribute(eisner_kernel,
                         cudaFuncAttributeMaxDynamicSharedMemorySize, smem_bytes);
    eisner_kernel<<<B, 1024, smem_bytes>>>(vin, out, has_bt, score_elems);
}

// round 4
// speedup vs baseline: 1.3828x; 1.3828x over previous
#include <cuda_runtime.h>

#define NN 128
#define TRI (NN * (NN + 1) / 2)   // 8256 cells per triangular table

__device__ __forceinline__ int triRow(int a) {
    // index of cell (a, a) in triangular packing
    return a * (2 * NN - a + 1) / 2;
}

#define NEGC    (-9999.0f)
#define THRESHC (-9000.0f)

// Chart storage: two float2 tables over triangular cells.
//   R[c] = (T00[c], T11[c])
//   P[c] = (T10[c], T01[c])

// One DP step for span width k, with G lanes cooperating per span.
template<int G>
__device__ __forceinline__ void step_body(
    const float2* __restrict__ R, const float2* __restrict__ P,
    float2* __restrict__ WR, float2* __restrict__ WP,
    const float* __restrict__ vin,
    float* __restrict__ outS, float* __restrict__ outB,
    int has_bt, int k, int tid)
{
    const int nspans = NN - k;
    // whole-warp early out (uniform across the warp)
    if (((tid & ~31) / G) >= nspans) return;

    const int gid_raw = tid / G;
    const int lig = tid % G;
    const bool lead = (lig == 0) && (gid_raw < nspans);
    const int i = min(gid_raw, nspans - 1);   // clamp dup groups (writes gated by lead)
    const int j = i + k;

    const float vL = vin[j * NN + i];   // left arc  (head j)
    const float vR = vin[i * NN + j];   // right arc (head i)
    const int rpi = triRow(i);

    const float NINF = __int_as_float(0xff800000);
    float v00 = NINF, v10 = NINF, v01 = NINF, v11 = NINF;
    int   m00 = NN,   m10 = NN,   m01 = NN,   m11 = NN;

    // incremental triangular indices: q = i + m, m = lig, lig+G, ...
    int m   = lig;
    int q0  = i + lig;
    int A   = triRow(q0) + (j - q0);        // tri(q, j)
    int B   = A + (NN - 1 - q0);            // tri(q+1, j)
    int dA  = (G * (257 - 2 * q0 - G)) / 2 - G;   // A(next) - A(cur)
    int idx = rpi + lig;                    // rpi + m

    #pragma unroll 2
    for (; m < k; m += G) {
        const float2 r_idx = R[idx];        // (T00[idx], T11[idx])
        const float  s01b  = P[B].y;        // T01[B]
        const float base = r_idx.y + s01b;
        // preserve reference rounding order: ((s11+s01)+v)+5.0
        float a0 = (base + vL) + 5.0f;
        float a1 = (base + vR) + 5.0f;
        if (a0 > v00) { v00 = a0; m00 = m; }
        if (a1 > v10) { v10 = a1; m10 = m; }
        if (m >= 1) {
            const float2 p_idx = P[idx];    // (T10[idx], T01[idx])
            const float2 r_A   = R[A];      // (T00[A],  T11[A])
            float c01 = p_idx.y + r_A.x;
            float c11 = p_idx.x + r_A.y;
            if (c01 > v01) { v01 = c01; m01 = m; }
            if (c11 > v11) { v11 = c11; m11 = m; }
        }
        A += dA; B += dA - G; dA -= G * G; idx += G;
    }

    if (G > 1) {
        // value-only max butterflies
        const float o00 = v00, o10 = v10, o01 = v01, o11 = v11;
        #pragma unroll
        for (int off = G / 2; off; off >>= 1) {
            v00 = fmaxf(v00, __shfl_xor_sync(0xffffffffu, v00, off));
            v10 = fmaxf(v10, __shfl_xor_sync(0xffffffffu, v10, off));
            v01 = fmaxf(v01, __shfl_xor_sync(0xffffffffu, v01, off));
            v11 = fmaxf(v11, __shfl_xor_sync(0xffffffffu, v11, off));
        }
        // min-index among value-ties (exact first-occurrence argmax)
        m00 = (o00 == v00) ? m00 : 0x7fffffff;
        m10 = (o10 == v10) ? m10 : 0x7fffffff;
        m01 = (o01 == v01) ? m01 : 0x7fffffff;
        m11 = (o11 == v11) ? m11 : 0x7fffffff;
        #pragma unroll
        for (int off = G / 2; off; off >>= 1) {
            m00 = min(m00, __shfl_xor_sync(0xffffffffu, m00, off));
            m10 = min(m10, __shfl_xor_sync(0xffffffffu, m10, off));
            m01 = min(m01, __shfl_xor_sync(0xffffffffu, m01, off));
            m11 = min(m11, __shfl_xor_sync(0xffffffffu, m11, off));
        }
    }

    if (lead) {
        // sequential-update quirks of the reference:
        // (0,1) at q=i sees the (0,0) cell after ONLY the q=i update
        float base0 = R[rpi].y + P[rpi + (NN - i) + (k - 1)].y;
        float p000 = (base0 + vL) + 5.0f;
        p000 = fmaxf(p000, NEGC);
        const float part00 = (p000 > THRESHC) ? p000 : NEGC;
        if (part00 > v01 || (part00 == v01 && 0 < m01)) { v01 = part00; m01 = 0; }
        // (1,1) at q=j sees the fully updated (1,0) cell
        const float new10 = (v10 > THRESHC) ? v10 : NEGC;
        if (new10 > v11) { v11 = new10; m11 = k; }

        const float s00 = (v00 > THRESHC) ? v00 : NEGC;
        const float s10 = (v10 > THRESHC) ? v10 : NEGC;
        const float s01 = (v01 > THRESHC) ? v01 : NEGC;
        const float s11 = (v11 > THRESHC) ? v11 : NEGC;
        const int t00 = (v00 > THRESHC) ? (i + m00) : 0;
        const int t10 = (v10 > THRESHC) ? (i + m10) : 0;
        const int t01 = (v01 > THRESHC) ? (i + m01) : 0;
        const int t11 = (v11 > THRESHC) ? (i + m11) : 0;

        const int tij = rpi + k;   // tri(i, j)
        WR[tij] = make_float2(s00, s11);
        WP[tij] = make_float2(s10, s01);

        const size_t o = ((size_t)(i * NN + j)) * 4;
        outS[o + 0] = s00; outS[o + 1] = s01;
        outS[o + 2] = s10; outS[o + 3] = s11;
        if (has_bt) {
            outB[o + 0] = (float)t00; outB[o + 1] = (float)t01;
            outB[o + 2] = (float)t10; outB[o + 3] = (float)t11;
        }
    }
}

__global__ void __launch_bounds__(512, 1)
eisner_kernel(const float* __restrict__ vin_all,
              float* __restrict__ out,
              int has_bt, int bt_off)
{
    extern __shared__ float sm[];
    float2* R = (float2*)sm;             // (T00, T11)
    float2* P = (float2*)(sm + 2 * TRI); // (T10, T01)

    const int b = blockIdx.x;
    const float* __restrict__ vin = vin_all + (size_t)b * NN * NN;
    float* __restrict__ outS = out + (size_t)b * NN * NN * 4;
    float* __restrict__ outB = out + (size_t)bt_off + (size_t)b * NN * NN * 4;

    const int tid = threadIdx.x;

    // ---- init: all cells NEG, diagonal = 0 ----
    for (int t = tid; t < 4 * TRI; t += blockDim.x) sm[t] = NEGC;
    __syncthreads();
    for (int i = tid; i < NN; i += blockDim.x) {
        int d = triRow(i);
        R[d] = make_float2(0.0f, 0.0f);
        P[d] = make_float2(0.0f, 0.0f);
    }
    // ---- init output: scores = NEG (diag 0), backtrace = 0 ----
    for (int t = tid; t < NN * NN * 4; t += blockDim.x) {
        int i = t >> 9;               // t / (NN*4)
        int j = (t >> 2) & (NN - 1);  // (t/4) % NN
        outS[t] = (i == j) ? 0.0f : NEGC;
    }
    if (has_bt) {
        for (int t = tid; t < NN * NN * 4; t += blockDim.x) outB[t] = 0.0f;
    }
    __syncthreads();

    // G policy (round-2 proven): k<=12:G1, <=24:G2, <=64:G4, <=96:G8, else G16
    for (int k = 1; k < NN; ++k) {
        if (k <= 12)
            step_body<1 >(R, P, R, P, vin, outS, outB, has_bt, k, tid);
        else if (k <= 24)
            step_body<2 >(R, P, R, P, vin, outS, outB, has_bt, k, tid);
        else if (k <= 64)
            step_body<4 >(R, P, R, P, vin, outS, outB, has_bt, k, tid);
        else if (k <= 96)
            step_body<8 >(R, P, R, P, vin, outS, outB, has_bt, k, tid);
        else
            step_body<16>(R, P, R, P, vin, outS, outB, has_bt, k, tid);
        __syncthreads();
    }
}

extern "C" void kernel_launch(void* const* d_in, const int* in_sizes, int n_in,
                              void* d_out, int out_size)
{
    const float* vin = (const float*)d_in[0];
    float* out = (float*)d_out;
    const int B = in_sizes[0] / (NN * NN);          // 64
    const int score_elems = B * NN * NN * 4;        // scores region size
    const int has_bt = (out_size >= 2 * score_elems) ? 1 : 0;

    const int smem_bytes = 4 * TRI * sizeof(float); // 132096 B
    cudaFuncSetAttribute(eisner_kernel,
                         cudaFuncAttributeMaxDynamicSharedMemorySize, smem_bytes);
    eisner_kernel<<<B, 512, smem_bytes>>>(vin, out, has_bt, score_elems);
}